// round 14
// baseline (speedup 1.0000x reference)
#include <cuda_runtime.h>
#include <cuda_fp16.h>
#include <cstdint>

// B=128, U=64, A=64. fp16 mma.sync m16n8k16 single plane; ldmatrix B operands.
// cg channel folded to rank-1 epilogue FFMA (wcg). asum fused into spP kernel.
// CTA = 2 independent 128-thread halves; persistent; cp.async double-buffered.

#define NBA 8192

__device__ float g_cgT[NBA * 64];                                // [ba][u] fp32
__device__ __align__(16) uint32_t g_rP[(size_t)NBA * 2048];      // [ba][u*32+c2]
__device__ __align__(16) uint32_t g_msgsP[(size_t)NBA * 2048];
__device__ float g_P[128 * 4096];
__device__ __align__(16) uint32_t g_wfrag[45056];
__device__ float g_wcg[6 * 64];

#define O_PHI1_W2 0
#define O_PHIK_W1(i) (2048 + (i) * 2048)
#define O_PHIK_W2(i) (10240 + (i) * 2048)
#define O_G1_W1 18432
#define O_G1_W2 20480
#define O_GK_W1(i) (22528 + (i) * 4096)
#define O_GK_W2(i) (34816 + (i) * 2048)
#define O_G5_W1 40960

#define CP_ASYNC16(dst, src) asm volatile("cp.async.cg.shared.global [%0], [%1], 16;" :: "r"(dst), "l"(src))
#define CP_COMMIT()          asm volatile("cp.async.commit_group;" ::: "memory")
#define CP_WAIT1()           asm volatile("cp.async.wait_group 1;" ::: "memory")
#define BARH(id)             asm volatile("bar.sync %0, 128;" :: "r"(id) : "memory")
#define LDM4(r0, r1, r2, r3, a) asm volatile( \
    "ldmatrix.sync.aligned.m8n8.x4.shared.b16 {%0,%1,%2,%3}, [%4];" \
    : "=r"(r0), "=r"(r1), "=r"(r2), "=r"(r3) : "r"(a))

__device__ __forceinline__ uint32_t packh(float lo, float hi) {
    return (uint32_t)__half_as_ushort(__float2half_rn(lo)) |
           ((uint32_t)__half_as_ushort(__float2half_rn(hi)) << 16);
}
__device__ __forceinline__ void mma16816(float d[4], const uint4& a, uint32_t b0, uint32_t b1) {
    asm volatile("mma.sync.aligned.m16n8k16.row.col.f32.f16.f16.f32 "
                 "{%0,%1,%2,%3}, {%4,%5,%6,%7}, {%8,%9}, {%0,%1,%2,%3};\n"
                 : "+f"(d[0]), "+f"(d[1]), "+f"(d[2]), "+f"(d[3])
                 : "r"(a.x), "r"(a.y), "r"(a.z), "r"(a.w), "r"(b0), "r"(b1));
}

// ---------------- prep: fp16 A-fragments + wcg vectors -----------------------
// types: 0 C=64 direct; 1 stride65 skip col0; 4 stride65 skip col0 *(-1/63);
//        5 C=128, cols>=64 *(-1/63)
__global__ void prep_kernel(const float* __restrict__ phi1W1, const float* __restrict__ phi1W2,
                            const float* __restrict__ phiKW1, const float* __restrict__ phiKW2,
                            const float* __restrict__ g1W1,   const float* __restrict__ g1W2,
                            const float* __restrict__ gKW1,   const float* __restrict__ gKW2,
                            const float* __restrict__ g5W1) {
    const int id = blockIdx.x;
    if (id >= 18) {   // wcg vectors
        int w = id - 18, o = threadIdx.x;
        if (o < 64) {
            float v;
            if (w == 0) v = phi1W1[o * 2] + phi1W1[o * 2 + 1];
            else if (w <= 4) v = phiKW1[(w - 1) * 4160 + o * 65];
            else v = g1W1[o * 65];
            g_wcg[w * 64 + o] = v;
        }
        return;
    }
    const float* src; int off, KB, type;
    if (id == 0)       { src = phi1W2;              off = O_PHI1_W2;       KB = 4; type = 0; }
    else if (id < 5)   { int i = id - 1;  src = phiKW1 + i * 4160; off = O_PHIK_W1(i); KB = 4; type = 1; }
    else if (id < 9)   { int i = id - 5;  src = phiKW2 + i * 4096; off = O_PHIK_W2(i); KB = 4; type = 0; }
    else if (id == 9)  { src = g1W1;                off = O_G1_W1;         KB = 4; type = 4; }
    else if (id == 10) { src = g1W2;                off = O_G1_W2;         KB = 4; type = 0; }
    else if (id < 14)  { int i = id - 11; src = gKW1 + i * 8192;  off = O_GK_W1(i);  KB = 8; type = 5; }
    else if (id < 17)  { int i = id - 14; src = gKW2 + i * 4096;  off = O_GK_W2(i);  KB = 4; type = 0; }
    else               { src = g5W1;                off = O_G5_W1;         KB = 8; type = 5; }

    const float ninv = -1.0f / 63.0f;
    const int total = KB * 512;
    for (int e = threadIdx.x; e < total; e += blockDim.x) {
        int strip = e / (KB * 128);
        int rem   = e % (KB * 128);
        int kt = rem / 128;
        int r3 = rem & 127;
        int lane = r3 >> 2, j = r3 & 3;
        int o  = strip * 16 + (lane >> 2) + 8 * (j & 1);
        int k0 = kt * 16 + (lane & 3) * 2 + 8 * (j >> 1);
        float w0, w1;
        if (type == 0)      { w0 = src[o * 64 + k0];  w1 = src[o * 64 + k0 + 1]; }
        else if (type == 5) { w0 = src[o * 128 + k0]; w1 = src[o * 128 + k0 + 1];
                              if (k0 >= 64) { w0 *= ninv; w1 *= ninv; } }
        else if (type == 1) { w0 = src[o * 65 + 1 + k0]; w1 = src[o * 65 + 2 + k0]; }
        else                { w0 = src[o * 65 + 1 + k0] * ninv; w1 = src[o * 65 + 2 + k0] * ninv; }
        g_wfrag[off + e] = packh(w0, w1);
    }
}

__global__ void cgt_kernel(const float* __restrict__ cg) {
    const int b = blockIdx.x;
    for (int j = threadIdx.x; j < 4096; j += 256) {
        int a = j >> 6, u = j & 63;
        g_cgT[(b * 64 + a) * 64 + u] = cg[b * 4096 + u * 64 + a];
    }
}

// ---------------- fused: sums over a (from msgs) + P = b1 + (Wagg/63)*S ------
__global__ void spP_kernel(const float* __restrict__ Wsrc, const float* __restrict__ b1,
                           int CW, int cOff) {
    __shared__ float sWT[64 * 65];
    __shared__ float sS2[64 * 68];
    const int b = blockIdx.x, t = threadIdx.x;
    for (int idx = t; idx < 4096; idx += 256) {
        int o = idx >> 6, c = idx & 63;
        sWT[c * 65 + o] = Wsrc[o * CW + cOff + c] * (1.0f / 63.0f);
    }
    // phase 1: sums over a of packed msgs
    {
        float s0[8], s1[8];
        const uint32_t* ps[8];
#pragma unroll
        for (int k = 0; k < 8; ++k) {
            s0[k] = 0.f; s1[k] = 0.f;
            ps[k] = g_msgsP + (size_t)b * 131072 + (t + k * 256);
        }
        for (int a = 0; a < 64; ++a) {
#pragma unroll
            for (int k = 0; k < 8; ++k) {
                uint32_t h = ps[k][(size_t)a * 2048];
                __half2 hv = *reinterpret_cast<const __half2*>(&h);
                float2 f = __half22float2(hv);
                s0[k] += f.x; s1[k] += f.y;
            }
        }
#pragma unroll
        for (int k = 0; k < 8; ++k) {
            int e = t + k * 256, u = e >> 5, c2 = e & 31;
            sS2[(2 * c2) * 68 + u]     = s0[k];
            sS2[(2 * c2 + 1) * 68 + u] = s1[k];
        }
    }
    __syncthreads();
    // phase 2: P GEMM
    const int o = t & 63, ublk = t >> 6;
    float acc[16];
    float bv = __ldg(b1 + o);
#pragma unroll
    for (int i = 0; i < 16; ++i) acc[i] = bv;
    const float4* S4 = (const float4*)sS2;
#pragma unroll 4
    for (int c = 0; c < 64; ++c) {
        float w = sWT[c * 65 + o];
#pragma unroll
        for (int i = 0; i < 4; ++i) {
            float4 s = S4[c * 17 + ublk * 4 + i];
            acc[i * 4 + 0] += w * s.x; acc[i * 4 + 1] += w * s.y;
            acc[i * 4 + 2] += w * s.z; acc[i * 4 + 3] += w * s.w;
        }
    }
    float4* P4 = (float4*)(g_P + b * 4096 + o * 64 + ublk * 16);
#pragma unroll
    for (int i = 0; i < 4; ++i)
        P4[i] = make_float4(acc[i * 4], acc[i * 4 + 1], acc[i * 4 + 2], acc[i * 4 + 3]);
}

// ---------------- cp.async prefetch ------------------------------------------
template<int MODE, int S1>
__device__ __forceinline__ void prefetch_slice(uint32_t dstB, int ba, int t2) {
    const uint32_t* rP = g_rP + (size_t)ba * 2048;
    const uint32_t* mP = g_msgsP + (size_t)ba * 2048;
    if (MODE == 3) {
        for (int cc = t2; cc < 64 * 16; cc += 128) {
            int row = cc >> 4, ch = cc & 15;
            const uint32_t* src = (ch < 8) ? (rP + row * 32 + ch * 4)
                                           : (mP + row * 32 + (ch - 8) * 4);
            CP_ASYNC16(dstB + (uint32_t)(row * S1 + ch * 4) * 4u, src);
        }
    } else {
        const uint32_t* base = (MODE == 1) ? rP : mP;
        for (int cc = t2; cc < 64 * 8; cc += 128) {
            int row = cc >> 3, ch = cc & 7;
            CP_ASYNC16(dstB + (uint32_t)(row * S1 + ch * 4) * 4u, base + row * 32 + ch * 4);
        }
    }
}

// ---------------- layer kernel -----------------------------------------------
// MODE: 0 phi1 (no conv1 mma), 1 phiK, 2 gamma1, 3 gammaK/gamma5
template<int KB1, int MODE, bool FINAL>
__global__ void __launch_bounds__(256, 2) layer_kernel(const float* __restrict__ b1v,
                                                       const float* __restrict__ b2v,
                                                       int w1off, int w2off, int wcgIdx,
                                                       const float* __restrict__ w2raw,
                                                       float* __restrict__ dout) {
    constexpr bool RELU2 = (MODE >= 2);
    constexpr int S1 = KB1 * 8 + 4;
    constexpr int BUFU = (KB1 > 0) ? 64 * S1 : 0;
    constexpr int W1U = (KB1 > 0) ? KB1 * 512 : 0;
    extern __shared__ uint32_t sm[];
    uint32_t* sW1f = sm;
    uint32_t* sX   = sW1f + W1U;
    uint32_t* sH   = sX + 4 * BUFU;
    float*    sRed = (float*)sH;

    const int t = threadIdx.x;
    const int warp = t >> 5, lane = t & 31, q = lane & 3, g = lane >> 2;
    const int half = warp >> 2, wl = warp & 3;
    const int t2 = t & 127;
    const int o_r = wl * 16 + g, o_r8 = o_r + 8;
    const bool geven = ((g & 1) == 0);
    const float inv = 1.0f / 63.0f;
    const int barid = 1 + half;
    const int row_lane = (lane & 7) + ((lane >> 4) << 3);
    const int kb_off = ((lane >> 3) & 1) * 4;

    uint32_t smbase;
    asm("{ .reg .u64 tmp; cvta.to.shared.u64 tmp, %1; cvt.u32.u64 %0, tmp; }"
        : "=r"(smbase) : "l"(sm));
    const uint32_t xbyte = smbase + (uint32_t)W1U * 4u;
    const uint32_t hbyte = smbase + (uint32_t)(W1U + 4 * BUFU + half * 2304) * 4u;
    uint32_t* sHh = sH + half * 2304;

    if (KB1 > 0) {
        const uint4* gw1 = (const uint4*)(g_wfrag + w1off);
        uint4* d1 = (uint4*)sW1f;
        for (int i = t; i < KB1 * 128; i += 256) d1[i] = gw1[i];
    }
    uint4 W2r[4];
    if (!FINAL) {
        const uint4* gw2 = (const uint4*)(g_wfrag + w2off);
#pragma unroll
        for (int kt = 0; kt < 4; ++kt) W2r[kt] = gw2[wl * 128 + kt * 32 + lane];
    }
    float bA1 = 0.f, bB1 = 0.f, bA2 = 0.f, bB2 = 0.f, w2a = 0.f, w2b = 0.f, bF = 0.f;
    float wA = 0.f, wB = 0.f;
    if (MODE < 2)  { bA1 = __ldg(b1v + o_r); bB1 = __ldg(b1v + o_r8); }
    if (MODE <= 2) { wA = g_wcg[wcgIdx * 64 + o_r]; wB = g_wcg[wcgIdx * 64 + o_r8]; }
    if (!FINAL)    { bA2 = __ldg(b2v + o_r); bB2 = __ldg(b2v + o_r8); }
    if (FINAL)     { w2a = __ldg(w2raw + o_r); w2b = __ldg(w2raw + o_r8); bF = __ldg(b2v); }

    {
        int tot = 4 * BUFU + (FINAL ? 512 : 2 * 2304);
        for (int i = t; i < tot; i += 256) sX[i] = 0;
    }
    __syncthreads();

    const int stride2 = gridDim.x * 2;
    const int stream = blockIdx.x * 2 + half;
    int o = 0;
    if (KB1 > 0) {
        if (stream < NBA)
            prefetch_slice<MODE, S1>(xbyte + (uint32_t)((half * 2) * BUFU) * 4u, stream, t2);
        CP_COMMIT();
    }

    uint32_t xadr0[4], hadr0[4];
#pragma unroll
    for (int ntp = 0; ntp < 4; ++ntp) {
        xadr0[ntp] = (uint32_t)(((ntp * 16 + row_lane) * S1 + kb_off) * 4);
        hadr0[ntp] = hbyte + (uint32_t)(((ntp * 16 + row_lane) * 36 + kb_off) * 4);
    }

    for (int ba = stream; ba < NBA; ba += stride2) {
        const int b = ba >> 6;
        if (KB1 > 0) {
            int nxt = ba + stride2;
            if (nxt < NBA)
                prefetch_slice<MODE, S1>(xbyte + (uint32_t)((half * 2 + (o ^ 1)) * BUFU) * 4u, nxt, t2);
            CP_COMMIT();
            CP_WAIT1();
            BARH(barid);
        }
        const uint32_t bufB = xbyte + (uint32_t)((half * 2 + o) * BUFU) * 4u;

        // cg values for this slice (epilogue rank-1 fold)
        float2 cg2[8];
        if (MODE <= 2) {
            const float* cgp = g_cgT + ba * 64;
#pragma unroll
            for (int nt = 0; nt < 8; ++nt)
                cg2[nt] = __ldg((const float2*)(cgp + nt * 8 + q * 2));
        }

        // ---- conv1 ----
        float acc[8][4];
#pragma unroll
        for (int nt = 0; nt < 8; ++nt)
#pragma unroll
            for (int j = 0; j < 4; ++j) acc[nt][j] = 0.f;
        if (KB1 > 0) {
            const uint4* A1 = (const uint4*)sW1f + wl * (KB1 * 32);
#pragma unroll
            for (int kt = 0; kt < KB1; ++kt) {
                uint4 Ah = A1[kt * 32 + lane];
#pragma unroll
                for (int ntp = 0; ntp < 4; ++ntp) {
                    uint32_t b0a, b1a, b0b, b1b;
                    LDM4(b0a, b1a, b0b, b1b, bufB + xadr0[ntp] + kt * 32);
                    mma16816(acc[2 * ntp],     Ah, b0a, b1a);
                    mma16816(acc[2 * ntp + 1], Ah, b0b, b1b);
                }
            }
        }
        if (MODE >= 2) {
            const float* Pb = g_P + b * 4096;
#pragma unroll
            for (int nt = 0; nt < 8; ++nt) {
                int u0 = nt * 8 + q * 2;
                float2 pa = __ldg((const float2*)(Pb + o_r * 64 + u0));
                float2 pb = __ldg((const float2*)(Pb + o_r8 * 64 + u0));
                acc[nt][0] += pa.x; acc[nt][1] += pa.y;
                acc[nt][2] += pb.x; acc[nt][3] += pb.y;
            }
        } else {
#pragma unroll
            for (int nt = 0; nt < 8; ++nt) {
                acc[nt][0] += bA1; acc[nt][1] += bA1;
                acc[nt][2] += bB1; acc[nt][3] += bB1;
            }
        }
        if (MODE <= 2) {
#pragma unroll
            for (int nt = 0; nt < 8; ++nt) {
                acc[nt][0] += wA * cg2[nt].x; acc[nt][1] += wA * cg2[nt].y;
                acc[nt][2] += wB * cg2[nt].x; acc[nt][3] += wB * cg2[nt].y;
            }
        }
#pragma unroll
        for (int nt = 0; nt < 8; ++nt)
#pragma unroll
            for (int j = 0; j < 4; ++j) acc[nt][j] = fmaxf(acc[nt][j], 0.0f);
        float SA = 0.f, SB = 0.f;
#pragma unroll
        for (int nt = 0; nt < 8; ++nt) { SA += acc[nt][0] + acc[nt][1]; SB += acc[nt][2] + acc[nt][3]; }
        SA += __shfl_xor_sync(0xffffffffu, SA, 1); SA += __shfl_xor_sync(0xffffffffu, SA, 2);
        SB += __shfl_xor_sync(0xffffffffu, SB, 1); SB += __shfl_xor_sync(0xffffffffu, SB, 2);

        if (!FINAL) {
            // post + pair-pack into H rows [u][c2]
#pragma unroll
            for (int nt = 0; nt < 8; ++nt) {
                float t0, t1, t2v, t3;
                if (wl >= 2) {
                    t0 = (SA - acc[nt][0]) * inv; t1 = (SA - acc[nt][1]) * inv;
                    t2v = (SB - acc[nt][2]) * inv; t3 = (SB - acc[nt][3]) * inv;
                } else { t0 = acc[nt][0]; t1 = acc[nt][1]; t2v = acc[nt][2]; t3 = acc[nt][3]; }
                float p0 = __shfl_xor_sync(0xffffffffu, t0, 4);
                float p1 = __shfl_xor_sync(0xffffffffu, t1, 4);
                float p2 = __shfl_xor_sync(0xffffffffu, t2v, 4);
                float p3 = __shfl_xor_sync(0xffffffffu, t3, 4);
                float v0a, v0b, v1a, v1b; int c2;
                if (geven) { c2 = o_r >> 1;        v0a = t0; v0b = p0; v1a = t1; v1b = p1; }
                else       { c2 = (o_r8 - 1) >> 1; v0a = p2; v0b = t2v; v1a = p3; v1b = t3; }
                int u0 = nt * 8 + q * 2;
                sHh[u0 * 36 + c2]       = packh(v0a, v0b);
                sHh[(u0 + 1) * 36 + c2] = packh(v1a, v1b);
            }
            BARH(barid);

            // ---- conv2 ----
            float a2[8][4];
#pragma unroll
            for (int nt = 0; nt < 8; ++nt)
#pragma unroll
                for (int j = 0; j < 4; ++j) a2[nt][j] = 0.f;
#pragma unroll
            for (int kt = 0; kt < 4; ++kt) {
#pragma unroll
                for (int ntp = 0; ntp < 4; ++ntp) {
                    uint32_t b0a, b1a, b0b, b1b;
                    LDM4(b0a, b1a, b0b, b1b, hadr0[ntp] + kt * 32);
                    mma16816(a2[2 * ntp],     W2r[kt], b0a, b1a);
                    mma16816(a2[2 * ntp + 1], W2r[kt], b0b, b1b);
                }
            }
#pragma unroll
            for (int nt = 0; nt < 8; ++nt) {
                a2[nt][0] += bA2; a2[nt][1] += bA2;
                a2[nt][2] += bB2; a2[nt][3] += bB2;
            }
            if (RELU2) {
#pragma unroll
                for (int nt = 0; nt < 8; ++nt)
#pragma unroll
                    for (int j = 0; j < 4; ++j) a2[nt][j] = fmaxf(a2[nt][j], 0.0f);
            }
            float S2A = 0.f, S2B = 0.f;
#pragma unroll
            for (int nt = 0; nt < 8; ++nt) { S2A += a2[nt][0] + a2[nt][1]; S2B += a2[nt][2] + a2[nt][3]; }
            S2A += __shfl_xor_sync(0xffffffffu, S2A, 1); S2A += __shfl_xor_sync(0xffffffffu, S2A, 2);
            S2B += __shfl_xor_sync(0xffffffffu, S2B, 1); S2B += __shfl_xor_sync(0xffffffffu, S2B, 2);

            uint32_t* gout = (RELU2 ? g_rP : g_msgsP) + (size_t)ba * 2048;
#pragma unroll
            for (int nt = 0; nt < 8; ++nt) {
                float t0, t1, t2v, t3;
                if (wl >= 2) {
                    t0 = (S2A - a2[nt][0]) * inv; t1 = (S2A - a2[nt][1]) * inv;
                    t2v = (S2B - a2[nt][2]) * inv; t3 = (S2B - a2[nt][3]) * inv;
                } else { t0 = a2[nt][0]; t1 = a2[nt][1]; t2v = a2[nt][2]; t3 = a2[nt][3]; }
                float p0 = __shfl_xor_sync(0xffffffffu, t0, 4);
                float p1 = __shfl_xor_sync(0xffffffffu, t1, 4);
                float p2 = __shfl_xor_sync(0xffffffffu, t2v, 4);
                float p3 = __shfl_xor_sync(0xffffffffu, t3, 4);
                float v0a, v0b, v1a, v1b; int c2;
                if (geven) { c2 = o_r >> 1;        v0a = t0; v0b = p0; v1a = t1; v1b = p1; }
                else       { c2 = (o_r8 - 1) >> 1; v0a = p2; v0b = t2v; v1a = p3; v1b = t3; }
                int u0 = nt * 8 + q * 2;
                gout[u0 * 32 + c2]       = packh(v0a, v0b);
                gout[(u0 + 1) * 32 + c2] = packh(v1a, v1b);
            }
            if (KB1 == 0) BARH(barid);     // protect H reuse next slice
        } else {
            // FINAL: GEMV partial + cross-warp reduce
#pragma unroll
            for (int nt = 0; nt < 8; ++nt) {
                float f0, f1, f2, f3;
                if (wl >= 2) {
                    f0 = (SA - acc[nt][0]) * inv; f1 = (SA - acc[nt][1]) * inv;
                    f2 = (SB - acc[nt][2]) * inv; f3 = (SB - acc[nt][3]) * inv;
                } else { f0 = acc[nt][0]; f1 = acc[nt][1]; f2 = acc[nt][2]; f3 = acc[nt][3]; }
                float p0 = w2a * f0 + w2b * f2;
                float p1 = w2a * f1 + w2b * f3;
                p0 += __shfl_xor_sync(0xffffffffu, p0, 4);
                p0 += __shfl_xor_sync(0xffffffffu, p0, 8);
                p0 += __shfl_xor_sync(0xffffffffu, p0, 16);
                p1 += __shfl_xor_sync(0xffffffffu, p1, 4);
                p1 += __shfl_xor_sync(0xffffffffu, p1, 8);
                p1 += __shfl_xor_sync(0xffffffffu, p1, 16);
                if (g == 0) {
                    int u0 = nt * 8 + q * 2;
                    sRed[half * 256 + wl * 64 + u0]     = p0;
                    sRed[half * 256 + wl * 64 + u0 + 1] = p1;
                }
            }
            BARH(barid);
            if (t2 < 64) {
                const float* R = sRed + half * 256;
                float sv = R[t2] + R[64 + t2] + R[128 + t2] + R[192 + t2];
                dout[b * 4096 + t2 * 64 + (ba & 63)] = sv + bF;
            }
            BARH(barid);
        }
        o ^= 1;
    }
}

// ---------------- launch -----------------------------------------------------
extern "C" void kernel_launch(void* const* d_in, const int* in_sizes, int n_in,
                              void* d_out, int out_size) {
    (void)in_sizes; (void)n_in; (void)out_size;
    const float* cg      = (const float*)d_in[0];
    const float* phi1_W1 = (const float*)d_in[1];
    const float* phi1_b1 = (const float*)d_in[2];
    const float* phi1_W2 = (const float*)d_in[3];
    const float* phi1_b2 = (const float*)d_in[4];
    const float* phiK_W1 = (const float*)d_in[5];
    const float* phiK_b1 = (const float*)d_in[6];
    const float* phiK_W2 = (const float*)d_in[7];
    const float* phiK_b2 = (const float*)d_in[8];
    const float* g1_W1   = (const float*)d_in[9];
    const float* g1_b1   = (const float*)d_in[10];
    const float* g1_W2   = (const float*)d_in[11];
    const float* g1_b2   = (const float*)d_in[12];
    const float* gK_W1   = (const float*)d_in[13];
    const float* gK_b1   = (const float*)d_in[14];
    const float* gK_W2   = (const float*)d_in[15];
    const float* gK_b2   = (const float*)d_in[16];
    const float* g5_W1   = (const float*)d_in[17];
    const float* g5_b1   = (const float*)d_in[18];
    const float* g5_W2   = (const float*)d_in[19];
    const float* g5_b2   = (const float*)d_in[20];
    float* out = (float*)d_out;

    auto smem_bytes = [](int KB1, bool fin) {
        int S1 = KB1 * 8 + 4;
        int BUFU = (KB1 > 0) ? 64 * S1 : 0;
        int W1U = (KB1 > 0) ? KB1 * 512 : 0;
        int u32s = W1U + 4 * BUFU + (fin ? 512 : 2 * 2304) + 16;
        return u32s * 4;
    };
    const int SM0 = smem_bytes(0, false);
    const int SM4 = smem_bytes(4, false);
    const int SM8 = smem_bytes(8, false);
    const int SMF = smem_bytes(8, true);

    cudaFuncSetAttribute(layer_kernel<0, 0, false>, cudaFuncAttributeMaxDynamicSharedMemorySize, SM0);
    cudaFuncSetAttribute(layer_kernel<4, 1, false>, cudaFuncAttributeMaxDynamicSharedMemorySize, SM4);
    cudaFuncSetAttribute(layer_kernel<4, 2, false>, cudaFuncAttributeMaxDynamicSharedMemorySize, SM4);
    cudaFuncSetAttribute(layer_kernel<8, 3, false>, cudaFuncAttributeMaxDynamicSharedMemorySize, SM8);
    cudaFuncSetAttribute(layer_kernel<8, 3, true>,  cudaFuncAttributeMaxDynamicSharedMemorySize, SMF);

    prep_kernel<<<24, 256>>>(phi1_W1, phi1_W2, phiK_W1, phiK_W2, g1_W1, g1_W2, gK_W1, gK_W2, g5_W1);
    cgt_kernel<<<128, 256>>>(cg);

    const int G = 296;

    layer_kernel<0, 0, false><<<G, 256, SM0>>>(phi1_b1, phi1_b2, 0, O_PHI1_W2, 0, nullptr, nullptr);
    spP_kernel<<<128, 256>>>(g1_W1, g1_b1, 65, 1);
    layer_kernel<4, 2, false><<<G, 256, SM4>>>(nullptr, g1_b2, O_G1_W1, O_G1_W2, 5, nullptr, nullptr);

    for (int i = 0; i < 4; ++i) {
        layer_kernel<4, 1, false><<<G, 256, SM4>>>(phiK_b1 + i * 64, phiK_b2 + i * 64,
                                                   O_PHIK_W1(i), O_PHIK_W2(i), 1 + i,
                                                   nullptr, nullptr);
        if (i < 3) {
            spP_kernel<<<128, 256>>>(gK_W1 + i * 8192, gK_b1 + i * 64, 128, 64);
            layer_kernel<8, 3, false><<<G, 256, SM8>>>(nullptr, gK_b2 + i * 64,
                                                       O_GK_W1(i), O_GK_W2(i), 0,
                                                       nullptr, nullptr);
        } else {
            spP_kernel<<<128, 256>>>(g5_W1, g5_b1, 128, 64);
            layer_kernel<8, 3, true><<<G, 256, SMF>>>(nullptr, g5_b2,
                                                      O_G5_W1, 0, 0, g5_W2, out);
        }
    }
}

// round 15
// speedup vs baseline: 1.1174x; 1.1174x over previous
#include <cuda_runtime.h>
#include <cuda_fp16.h>
#include <cstdint>

// B=128, U=64, A=64. fp16 mma.sync m16n8k16 single plane; ldmatrix B operands.
// cg channel folded to rank-1 epilogue FFMA (wcg). Separate asum (grid 1024) + pP.
// CTA = 2 independent 128-thread halves; persistent; cp.async double-buffered.

#define NBA 8192

__device__ float g_cgT[NBA * 64];                                // [ba][u] fp32
__device__ __align__(16) uint32_t g_rP[(size_t)NBA * 2048];      // [ba][u*32+c2]
__device__ __align__(16) uint32_t g_msgsP[(size_t)NBA * 2048];
__device__ float g_sums[128 * 4096];                             // [b][c][u]
__device__ float g_P[128 * 4096];
__device__ __align__(16) uint32_t g_wfrag[45056];
__device__ float g_wcg[6 * 64];

#define O_PHI1_W2 0
#define O_PHIK_W1(i) (2048 + (i) * 2048)
#define O_PHIK_W2(i) (10240 + (i) * 2048)
#define O_G1_W1 18432
#define O_G1_W2 20480
#define O_GK_W1(i) (22528 + (i) * 4096)
#define O_GK_W2(i) (34816 + (i) * 2048)
#define O_G5_W1 40960

#define CP_ASYNC16(dst, src) asm volatile("cp.async.cg.shared.global [%0], [%1], 16;" :: "r"(dst), "l"(src))
#define CP_COMMIT()          asm volatile("cp.async.commit_group;" ::: "memory")
#define CP_WAIT1()           asm volatile("cp.async.wait_group 1;" ::: "memory")
#define BARH(id)             asm volatile("bar.sync %0, 128;" :: "r"(id) : "memory")
#define LDM4(r0, r1, r2, r3, a) asm volatile( \
    "ldmatrix.sync.aligned.m8n8.x4.shared.b16 {%0,%1,%2,%3}, [%4];" \
    : "=r"(r0), "=r"(r1), "=r"(r2), "=r"(r3) : "r"(a))

__device__ __forceinline__ uint32_t packh(float lo, float hi) {
    return (uint32_t)__half_as_ushort(__float2half_rn(lo)) |
           ((uint32_t)__half_as_ushort(__float2half_rn(hi)) << 16);
}
__device__ __forceinline__ void mma16816(float d[4], const uint4& a, uint32_t b0, uint32_t b1) {
    asm volatile("mma.sync.aligned.m16n8k16.row.col.f32.f16.f16.f32 "
                 "{%0,%1,%2,%3}, {%4,%5,%6,%7}, {%8,%9}, {%0,%1,%2,%3};\n"
                 : "+f"(d[0]), "+f"(d[1]), "+f"(d[2]), "+f"(d[3])
                 : "r"(a.x), "r"(a.y), "r"(a.z), "r"(a.w), "r"(b0), "r"(b1));
}

// ---------------- prep: fp16 A-fragments + wcg vectors (verified R14) --------
__global__ void prep_kernel(const float* __restrict__ phi1W1, const float* __restrict__ phi1W2,
                            const float* __restrict__ phiKW1, const float* __restrict__ phiKW2,
                            const float* __restrict__ g1W1,   const float* __restrict__ g1W2,
                            const float* __restrict__ gKW1,   const float* __restrict__ gKW2,
                            const float* __restrict__ g5W1) {
    const int id = blockIdx.x;
    if (id >= 18) {
        int w = id - 18, o = threadIdx.x;
        if (o < 64) {
            float v;
            if (w == 0) v = phi1W1[o * 2] + phi1W1[o * 2 + 1];
            else if (w <= 4) v = phiKW1[(w - 1) * 4160 + o * 65];
            else v = g1W1[o * 65];
            g_wcg[w * 64 + o] = v;
        }
        return;
    }
    const float* src; int off, KB, type;
    if (id == 0)       { src = phi1W2;              off = O_PHI1_W2;       KB = 4; type = 0; }
    else if (id < 5)   { int i = id - 1;  src = phiKW1 + i * 4160; off = O_PHIK_W1(i); KB = 4; type = 1; }
    else if (id < 9)   { int i = id - 5;  src = phiKW2 + i * 4096; off = O_PHIK_W2(i); KB = 4; type = 0; }
    else if (id == 9)  { src = g1W1;                off = O_G1_W1;         KB = 4; type = 4; }
    else if (id == 10) { src = g1W2;                off = O_G1_W2;         KB = 4; type = 0; }
    else if (id < 14)  { int i = id - 11; src = gKW1 + i * 8192;  off = O_GK_W1(i);  KB = 8; type = 5; }
    else if (id < 17)  { int i = id - 14; src = gKW2 + i * 4096;  off = O_GK_W2(i);  KB = 4; type = 0; }
    else               { src = g5W1;                off = O_G5_W1;         KB = 8; type = 5; }

    const float ninv = -1.0f / 63.0f;
    const int total = KB * 512;
    for (int e = threadIdx.x; e < total; e += blockDim.x) {
        int strip = e / (KB * 128);
        int rem   = e % (KB * 128);
        int kt = rem / 128;
        int r3 = rem & 127;
        int lane = r3 >> 2, j = r3 & 3;
        int o  = strip * 16 + (lane >> 2) + 8 * (j & 1);
        int k0 = kt * 16 + (lane & 3) * 2 + 8 * (j >> 1);
        float w0, w1;
        if (type == 0)      { w0 = src[o * 64 + k0];  w1 = src[o * 64 + k0 + 1]; }
        else if (type == 5) { w0 = src[o * 128 + k0]; w1 = src[o * 128 + k0 + 1];
                              if (k0 >= 64) { w0 *= ninv; w1 *= ninv; } }
        else if (type == 1) { w0 = src[o * 65 + 1 + k0]; w1 = src[o * 65 + 2 + k0]; }
        else                { w0 = src[o * 65 + 1 + k0] * ninv; w1 = src[o * 65 + 2 + k0] * ninv; }
        g_wfrag[off + e] = packh(w0, w1);
    }
}

__global__ void cgt_kernel(const float* __restrict__ cg) {
    const int b = blockIdx.x;
    for (int j = threadIdx.x; j < 4096; j += 256) {
        int a = j >> 6, u = j & 63;
        g_cgT[(b * 64 + a) * 64 + u] = cg[b * 4096 + u * 64 + a];
    }
}

// ---------------- sum over a of packed msgs ([u][c2] layout; verified R13) ----
__global__ void asum_kernel() {
    const int b = blockIdx.x >> 3;
    const int e = (blockIdx.x & 7) * 256 + threadIdx.x;   // u*32 + c2
    const uint32_t* p0 = g_msgsP + (size_t)b * 131072 + e;
    float s0 = 0.f, s1 = 0.f;
#pragma unroll 8
    for (int a = 0; a < 64; ++a) {
        uint32_t h = p0[(size_t)a * 2048];
        __half2 hv = *reinterpret_cast<const __half2*>(&h);
        float2 f = __half22float2(hv);
        s0 += f.x; s1 += f.y;
    }
    int u = e >> 5, c2 = e & 31;
    g_sums[b * 4096 + (2 * c2) * 64 + u]     = s0;
    g_sums[b * 4096 + (2 * c2 + 1) * 64 + u] = s1;
}

// ---------------- per-b precompute: P = bias1 + (Wagg/63)*S (verified R11) ----
__global__ void pP_kernel(const float* __restrict__ Wsrc, const float* __restrict__ b1,
                          int CW, int cOff) {
    __shared__ float sWT[64 * 65];
    __shared__ float sS2[4096];
    const int b = blockIdx.x, t = threadIdx.x;
    for (int idx = t; idx < 4096; idx += 256) {
        int o = idx >> 6, c = idx & 63;
        sWT[c * 65 + o] = Wsrc[o * CW + cOff + c] * (1.0f / 63.0f);
        sS2[idx] = g_sums[b * 4096 + idx];
    }
    __syncthreads();
    const int o = t & 63, ublk = t >> 6;
    float acc[16];
    float bv = __ldg(b1 + o);
#pragma unroll
    for (int i = 0; i < 16; ++i) acc[i] = bv;
    const float4* S4 = (const float4*)sS2;
#pragma unroll 4
    for (int c = 0; c < 64; ++c) {
        float w = sWT[c * 65 + o];
#pragma unroll
        for (int i = 0; i < 4; ++i) {
            float4 s = S4[c * 16 + ublk * 4 + i];
            acc[i * 4 + 0] += w * s.x; acc[i * 4 + 1] += w * s.y;
            acc[i * 4 + 2] += w * s.z; acc[i * 4 + 3] += w * s.w;
        }
    }
    float4* P4 = (float4*)(g_P + b * 4096 + o * 64 + ublk * 16);
#pragma unroll
    for (int i = 0; i < 4; ++i)
        P4[i] = make_float4(acc[i * 4], acc[i * 4 + 1], acc[i * 4 + 2], acc[i * 4 + 3]);
}

// ---------------- cp.async prefetch ------------------------------------------
template<int MODE, int S1>
__device__ __forceinline__ void prefetch_slice(uint32_t dstB, int ba, int t2) {
    const uint32_t* rP = g_rP + (size_t)ba * 2048;
    const uint32_t* mP = g_msgsP + (size_t)ba * 2048;
    if (MODE == 3) {
        for (int cc = t2; cc < 64 * 16; cc += 128) {
            int row = cc >> 4, ch = cc & 15;
            const uint32_t* src = (ch < 8) ? (rP + row * 32 + ch * 4)
                                           : (mP + row * 32 + (ch - 8) * 4);
            CP_ASYNC16(dstB + (uint32_t)(row * S1 + ch * 4) * 4u, src);
        }
    } else {
        const uint32_t* base = (MODE == 1) ? rP : mP;
        for (int cc = t2; cc < 64 * 8; cc += 128) {
            int row = cc >> 3, ch = cc & 7;
            CP_ASYNC16(dstB + (uint32_t)(row * S1 + ch * 4) * 4u, base + row * 32 + ch * 4);
        }
    }
}

// ---------------- layer kernel (verbatim R14) ---------------------------------
// MODE: 0 phi1 (no conv1 mma), 1 phiK, 2 gamma1, 3 gammaK/gamma5
template<int KB1, int MODE, bool FINAL>
__global__ void __launch_bounds__(256, 2) layer_kernel(const float* __restrict__ b1v,
                                                       const float* __restrict__ b2v,
                                                       int w1off, int w2off, int wcgIdx,
                                                       const float* __restrict__ w2raw,
                                                       float* __restrict__ dout) {
    constexpr bool RELU2 = (MODE >= 2);
    constexpr int S1 = KB1 * 8 + 4;
    constexpr int BUFU = (KB1 > 0) ? 64 * S1 : 0;
    constexpr int W1U = (KB1 > 0) ? KB1 * 512 : 0;
    extern __shared__ uint32_t sm[];
    uint32_t* sW1f = sm;
    uint32_t* sX   = sW1f + W1U;
    uint32_t* sH   = sX + 4 * BUFU;
    float*    sRed = (float*)sH;

    const int t = threadIdx.x;
    const int warp = t >> 5, lane = t & 31, q = lane & 3, g = lane >> 2;
    const int half = warp >> 2, wl = warp & 3;
    const int t2 = t & 127;
    const int o_r = wl * 16 + g, o_r8 = o_r + 8;
    const bool geven = ((g & 1) == 0);
    const float inv = 1.0f / 63.0f;
    const int barid = 1 + half;
    const int row_lane = (lane & 7) + ((lane >> 4) << 3);
    const int kb_off = ((lane >> 3) & 1) * 4;

    uint32_t smbase;
    asm("{ .reg .u64 tmp; cvta.to.shared.u64 tmp, %1; cvt.u32.u64 %0, tmp; }"
        : "=r"(smbase) : "l"(sm));
    const uint32_t xbyte = smbase + (uint32_t)W1U * 4u;
    const uint32_t hbyte = smbase + (uint32_t)(W1U + 4 * BUFU + half * 2304) * 4u;
    uint32_t* sHh = sH + half * 2304;

    if (KB1 > 0) {
        const uint4* gw1 = (const uint4*)(g_wfrag + w1off);
        uint4* d1 = (uint4*)sW1f;
        for (int i = t; i < KB1 * 128; i += 256) d1[i] = gw1[i];
    }
    uint4 W2r[4];
    if (!FINAL) {
        const uint4* gw2 = (const uint4*)(g_wfrag + w2off);
#pragma unroll
        for (int kt = 0; kt < 4; ++kt) W2r[kt] = gw2[wl * 128 + kt * 32 + lane];
    }
    float bA1 = 0.f, bB1 = 0.f, bA2 = 0.f, bB2 = 0.f, w2a = 0.f, w2b = 0.f, bF = 0.f;
    float wA = 0.f, wB = 0.f;
    if (MODE < 2)  { bA1 = __ldg(b1v + o_r); bB1 = __ldg(b1v + o_r8); }
    if (MODE <= 2) { wA = g_wcg[wcgIdx * 64 + o_r]; wB = g_wcg[wcgIdx * 64 + o_r8]; }
    if (!FINAL)    { bA2 = __ldg(b2v + o_r); bB2 = __ldg(b2v + o_r8); }
    if (FINAL)     { w2a = __ldg(w2raw + o_r); w2b = __ldg(w2raw + o_r8); bF = __ldg(b2v); }

    {
        int tot = 4 * BUFU + (FINAL ? 512 : 2 * 2304);
        for (int i = t; i < tot; i += 256) sX[i] = 0;
    }
    __syncthreads();

    const int stride2 = gridDim.x * 2;
    const int stream = blockIdx.x * 2 + half;
    int o = 0;
    if (KB1 > 0) {
        if (stream < NBA)
            prefetch_slice<MODE, S1>(xbyte + (uint32_t)((half * 2) * BUFU) * 4u, stream, t2);
        CP_COMMIT();
    }

    uint32_t xadr0[4], hadr0[4];
#pragma unroll
    for (int ntp = 0; ntp < 4; ++ntp) {
        xadr0[ntp] = (uint32_t)(((ntp * 16 + row_lane) * S1 + kb_off) * 4);
        hadr0[ntp] = hbyte + (uint32_t)(((ntp * 16 + row_lane) * 36 + kb_off) * 4);
    }

    for (int ba = stream; ba < NBA; ba += stride2) {
        const int b = ba >> 6;
        if (KB1 > 0) {
            int nxt = ba + stride2;
            if (nxt < NBA)
                prefetch_slice<MODE, S1>(xbyte + (uint32_t)((half * 2 + (o ^ 1)) * BUFU) * 4u, nxt, t2);
            CP_COMMIT();
            CP_WAIT1();
            BARH(barid);
        }
        const uint32_t bufB = xbyte + (uint32_t)((half * 2 + o) * BUFU) * 4u;

        float2 cg2[8];
        if (MODE <= 2) {
            const float* cgp = g_cgT + ba * 64;
#pragma unroll
            for (int nt = 0; nt < 8; ++nt)
                cg2[nt] = __ldg((const float2*)(cgp + nt * 8 + q * 2));
        }

        // ---- conv1 ----
        float acc[8][4];
#pragma unroll
        for (int nt = 0; nt < 8; ++nt)
#pragma unroll
            for (int j = 0; j < 4; ++j) acc[nt][j] = 0.f;
        if (KB1 > 0) {
            const uint4* A1 = (const uint4*)sW1f + wl * (KB1 * 32);
#pragma unroll
            for (int kt = 0; kt < KB1; ++kt) {
                uint4 Ah = A1[kt * 32 + lane];
#pragma unroll
                for (int ntp = 0; ntp < 4; ++ntp) {
                    uint32_t b0a, b1a, b0b, b1b;
                    LDM4(b0a, b1a, b0b, b1b, bufB + xadr0[ntp] + kt * 32);
                    mma16816(acc[2 * ntp],     Ah, b0a, b1a);
                    mma16816(acc[2 * ntp + 1], Ah, b0b, b1b);
                }
            }
        }
        if (MODE >= 2) {
            const float* Pb = g_P + b * 4096;
#pragma unroll
            for (int nt = 0; nt < 8; ++nt) {
                int u0 = nt * 8 + q * 2;
                float2 pa = __ldg((const float2*)(Pb + o_r * 64 + u0));
                float2 pb = __ldg((const float2*)(Pb + o_r8 * 64 + u0));
                acc[nt][0] += pa.x; acc[nt][1] += pa.y;
                acc[nt][2] += pb.x; acc[nt][3] += pb.y;
            }
        } else {
#pragma unroll
            for (int nt = 0; nt < 8; ++nt) {
                acc[nt][0] += bA1; acc[nt][1] += bA1;
                acc[nt][2] += bB1; acc[nt][3] += bB1;
            }
        }
        if (MODE <= 2) {
#pragma unroll
            for (int nt = 0; nt < 8; ++nt) {
                acc[nt][0] += wA * cg2[nt].x; acc[nt][1] += wA * cg2[nt].y;
                acc[nt][2] += wB * cg2[nt].x; acc[nt][3] += wB * cg2[nt].y;
            }
        }
#pragma unroll
        for (int nt = 0; nt < 8; ++nt)
#pragma unroll
            for (int j = 0; j < 4; ++j) acc[nt][j] = fmaxf(acc[nt][j], 0.0f);
        float SA = 0.f, SB = 0.f;
#pragma unroll
        for (int nt = 0; nt < 8; ++nt) { SA += acc[nt][0] + acc[nt][1]; SB += acc[nt][2] + acc[nt][3]; }
        SA += __shfl_xor_sync(0xffffffffu, SA, 1); SA += __shfl_xor_sync(0xffffffffu, SA, 2);
        SB += __shfl_xor_sync(0xffffffffu, SB, 1); SB += __shfl_xor_sync(0xffffffffu, SB, 2);

        if (!FINAL) {
#pragma unroll
            for (int nt = 0; nt < 8; ++nt) {
                float t0, t1, t2v, t3;
                if (wl >= 2) {
                    t0 = (SA - acc[nt][0]) * inv; t1 = (SA - acc[nt][1]) * inv;
                    t2v = (SB - acc[nt][2]) * inv; t3 = (SB - acc[nt][3]) * inv;
                } else { t0 = acc[nt][0]; t1 = acc[nt][1]; t2v = acc[nt][2]; t3 = acc[nt][3]; }
                float p0 = __shfl_xor_sync(0xffffffffu, t0, 4);
                float p1 = __shfl_xor_sync(0xffffffffu, t1, 4);
                float p2 = __shfl_xor_sync(0xffffffffu, t2v, 4);
                float p3 = __shfl_xor_sync(0xffffffffu, t3, 4);
                float v0a, v0b, v1a, v1b; int c2;
                if (geven) { c2 = o_r >> 1;        v0a = t0; v0b = p0; v1a = t1; v1b = p1; }
                else       { c2 = (o_r8 - 1) >> 1; v0a = p2; v0b = t2v; v1a = p3; v1b = t3; }
                int u0 = nt * 8 + q * 2;
                sHh[u0 * 36 + c2]       = packh(v0a, v0b);
                sHh[(u0 + 1) * 36 + c2] = packh(v1a, v1b);
            }
            BARH(barid);

            // ---- conv2 ----
            float a2[8][4];
#pragma unroll
            for (int nt = 0; nt < 8; ++nt)
#pragma unroll
                for (int j = 0; j < 4; ++j) a2[nt][j] = 0.f;
#pragma unroll
            for (int kt = 0; kt < 4; ++kt) {
#pragma unroll
                for (int ntp = 0; ntp < 4; ++ntp) {
                    uint32_t b0a, b1a, b0b, b1b;
                    LDM4(b0a, b1a, b0b, b1b, hadr0[ntp] + kt * 32);
                    mma16816(a2[2 * ntp],     W2r[kt], b0a, b1a);
                    mma16816(a2[2 * ntp + 1], W2r[kt], b0b, b1b);
                }
            }
#pragma unroll
            for (int nt = 0; nt < 8; ++nt) {
                a2[nt][0] += bA2; a2[nt][1] += bA2;
                a2[nt][2] += bB2; a2[nt][3] += bB2;
            }
            if (RELU2) {
#pragma unroll
                for (int nt = 0; nt < 8; ++nt)
#pragma unroll
                    for (int j = 0; j < 4; ++j) a2[nt][j] = fmaxf(a2[nt][j], 0.0f);
            }
            float S2A = 0.f, S2B = 0.f;
#pragma unroll
            for (int nt = 0; nt < 8; ++nt) { S2A += a2[nt][0] + a2[nt][1]; S2B += a2[nt][2] + a2[nt][3]; }
            S2A += __shfl_xor_sync(0xffffffffu, S2A, 1); S2A += __shfl_xor_sync(0xffffffffu, S2A, 2);
            S2B += __shfl_xor_sync(0xffffffffu, S2B, 1); S2B += __shfl_xor_sync(0xffffffffu, S2B, 2);

            uint32_t* gout = (RELU2 ? g_rP : g_msgsP) + (size_t)ba * 2048;
#pragma unroll
            for (int nt = 0; nt < 8; ++nt) {
                float t0, t1, t2v, t3;
                if (wl >= 2) {
                    t0 = (S2A - a2[nt][0]) * inv; t1 = (S2A - a2[nt][1]) * inv;
                    t2v = (S2B - a2[nt][2]) * inv; t3 = (S2B - a2[nt][3]) * inv;
                } else { t0 = a2[nt][0]; t1 = a2[nt][1]; t2v = a2[nt][2]; t3 = a2[nt][3]; }
                float p0 = __shfl_xor_sync(0xffffffffu, t0, 4);
                float p1 = __shfl_xor_sync(0xffffffffu, t1, 4);
                float p2 = __shfl_xor_sync(0xffffffffu, t2v, 4);
                float p3 = __shfl_xor_sync(0xffffffffu, t3, 4);
                float v0a, v0b, v1a, v1b; int c2;
                if (geven) { c2 = o_r >> 1;        v0a = t0; v0b = p0; v1a = t1; v1b = p1; }
                else       { c2 = (o_r8 - 1) >> 1; v0a = p2; v0b = t2v; v1a = p3; v1b = t3; }
                int u0 = nt * 8 + q * 2;
                gout[u0 * 32 + c2]       = packh(v0a, v0b);
                gout[(u0 + 1) * 32 + c2] = packh(v1a, v1b);
            }
            if (KB1 == 0) BARH(barid);
        } else {
#pragma unroll
            for (int nt = 0; nt < 8; ++nt) {
                float f0, f1, f2, f3;
                if (wl >= 2) {
                    f0 = (SA - acc[nt][0]) * inv; f1 = (SA - acc[nt][1]) * inv;
                    f2 = (SB - acc[nt][2]) * inv; f3 = (SB - acc[nt][3]) * inv;
                } else { f0 = acc[nt][0]; f1 = acc[nt][1]; f2 = acc[nt][2]; f3 = acc[nt][3]; }
                float p0 = w2a * f0 + w2b * f2;
                float p1 = w2a * f1 + w2b * f3;
                p0 += __shfl_xor_sync(0xffffffffu, p0, 4);
                p0 += __shfl_xor_sync(0xffffffffu, p0, 8);
                p0 += __shfl_xor_sync(0xffffffffu, p0, 16);
                p1 += __shfl_xor_sync(0xffffffffu, p1, 4);
                p1 += __shfl_xor_sync(0xffffffffu, p1, 8);
                p1 += __shfl_xor_sync(0xffffffffu, p1, 16);
                if (g == 0) {
                    int u0 = nt * 8 + q * 2;
                    sRed[half * 256 + wl * 64 + u0]     = p0;
                    sRed[half * 256 + wl * 64 + u0 + 1] = p1;
                }
            }
            BARH(barid);
            if (t2 < 64) {
                const float* R = sRed + half * 256;
                float sv = R[t2] + R[64 + t2] + R[128 + t2] + R[192 + t2];
                dout[b * 4096 + t2 * 64 + (ba & 63)] = sv + bF;
            }
            BARH(barid);
        }
        o ^= 1;
    }
}

// ---------------- launch -----------------------------------------------------
extern "C" void kernel_launch(void* const* d_in, const int* in_sizes, int n_in,
                              void* d_out, int out_size) {
    (void)in_sizes; (void)n_in; (void)out_size;
    const float* cg      = (const float*)d_in[0];
    const float* phi1_W1 = (const float*)d_in[1];
    const float* phi1_b1 = (const float*)d_in[2];
    const float* phi1_W2 = (const float*)d_in[3];
    const float* phi1_b2 = (const float*)d_in[4];
    const float* phiK_W1 = (const float*)d_in[5];
    const float* phiK_b1 = (const float*)d_in[6];
    const float* phiK_W2 = (const float*)d_in[7];
    const float* phiK_b2 = (const float*)d_in[8];
    const float* g1_W1   = (const float*)d_in[9];
    const float* g1_b1   = (const float*)d_in[10];
    const float* g1_W2   = (const float*)d_in[11];
    const float* g1_b2   = (const float*)d_in[12];
    const float* gK_W1   = (const float*)d_in[13];
    const float* gK_b1   = (const float*)d_in[14];
    const float* gK_W2   = (const float*)d_in[15];
    const float* gK_b2   = (const float*)d_in[16];
    const float* g5_W1   = (const float*)d_in[17];
    const float* g5_b1   = (const float*)d_in[18];
    const float* g5_W2   = (const float*)d_in[19];
    const float* g5_b2   = (const float*)d_in[20];
    float* out = (float*)d_out;

    auto smem_bytes = [](int KB1, bool fin) {
        int S1 = KB1 * 8 + 4;
        int BUFU = (KB1 > 0) ? 64 * S1 : 0;
        int W1U = (KB1 > 0) ? KB1 * 512 : 0;
        int u32s = W1U + 4 * BUFU + (fin ? 512 : 2 * 2304) + 16;
        return u32s * 4;
    };
    const int SM0 = smem_bytes(0, false);
    const int SM4 = smem_bytes(4, false);
    const int SM8 = smem_bytes(8, false);
    const int SMF = smem_bytes(8, true);

    cudaFuncSetAttribute(layer_kernel<0, 0, false>, cudaFuncAttributeMaxDynamicSharedMemorySize, SM0);
    cudaFuncSetAttribute(layer_kernel<4, 1, false>, cudaFuncAttributeMaxDynamicSharedMemorySize, SM4);
    cudaFuncSetAttribute(layer_kernel<4, 2, false>, cudaFuncAttributeMaxDynamicSharedMemorySize, SM4);
    cudaFuncSetAttribute(layer_kernel<8, 3, false>, cudaFuncAttributeMaxDynamicSharedMemorySize, SM8);
    cudaFuncSetAttribute(layer_kernel<8, 3, true>,  cudaFuncAttributeMaxDynamicSharedMemorySize, SMF);

    prep_kernel<<<24, 256>>>(phi1_W1, phi1_W2, phiK_W1, phiK_W2, g1_W1, g1_W2, gK_W1, gK_W2, g5_W1);
    cgt_kernel<<<128, 256>>>(cg);

    const int G = 296;

    layer_kernel<0, 0, false><<<G, 256, SM0>>>(phi1_b1, phi1_b2, 0, O_PHI1_W2, 0, nullptr, nullptr);
    asum_kernel<<<1024, 256>>>();
    pP_kernel<<<128, 256>>>(g1_W1, g1_b1, 65, 1);
    layer_kernel<4, 2, false><<<G, 256, SM4>>>(nullptr, g1_b2, O_G1_W1, O_G1_W2, 5, nullptr, nullptr);

    for (int i = 0; i < 4; ++i) {
        layer_kernel<4, 1, false><<<G, 256, SM4>>>(phiK_b1 + i * 64, phiK_b2 + i * 64,
                                                   O_PHIK_W1(i), O_PHIK_W2(i), 1 + i,
                                                   nullptr, nullptr);
        asum_kernel<<<1024, 256>>>();
        if (i < 3) {
            pP_kernel<<<128, 256>>>(gK_W1 + i * 8192, gK_b1 + i * 64, 128, 64);
            layer_kernel<8, 3, false><<<G, 256, SM8>>>(nullptr, gK_b2 + i * 64,
                                                       O_GK_W1(i), O_GK_W2(i), 0,
                                                       nullptr, nullptr);
        } else {
            pP_kernel<<<128, 256>>>(g5_W1, g5_b1, 128, 64);
            layer_kernel<8, 3, true><<<G, 256, SMF>>>(nullptr, g5_b2,
                                                      O_G5_W1, 0, 0, g5_W2, out);
        }
    }
}

// round 16
// speedup vs baseline: 1.2373x; 1.1073x over previous
#include <cuda_runtime.h>
#include <cuda_fp16.h>
#include <cstdint>

// B=128, U=64, A=64. fp16 mma.sync m16n8k16 single plane; ldmatrix B operands.
// cg folded to rank-1 epilogue FFMA. Output-channel permutation: fragment rows
// (g, g+8) = orig channels (wl*16+2g, wl*16+2g+1) -> shuffle-free epilogue pack.

#define NBA 8192

__device__ float g_cgT[NBA * 64];                                // [ba][u] fp32
__device__ __align__(16) uint32_t g_rP[(size_t)NBA * 2048];      // [ba][u*32+c2]
__device__ __align__(16) uint32_t g_msgsP[(size_t)NBA * 2048];
__device__ float g_sums[128 * 4096];                             // [b][c][u]
__device__ float g_P[128 * 4096];
__device__ __align__(16) uint32_t g_wfrag[45056];
__device__ float g_wcg[6 * 64];

#define O_PHI1_W2 0
#define O_PHIK_W1(i) (2048 + (i) * 2048)
#define O_PHIK_W2(i) (10240 + (i) * 2048)
#define O_G1_W1 18432
#define O_G1_W2 20480
#define O_GK_W1(i) (22528 + (i) * 4096)
#define O_GK_W2(i) (34816 + (i) * 2048)
#define O_G5_W1 40960

#define CP_ASYNC16(dst, src) asm volatile("cp.async.cg.shared.global [%0], [%1], 16;" :: "r"(dst), "l"(src))
#define CP_COMMIT()          asm volatile("cp.async.commit_group;" ::: "memory")
#define CP_WAIT1()           asm volatile("cp.async.wait_group 1;" ::: "memory")
#define BARH(id)             asm volatile("bar.sync %0, 128;" :: "r"(id) : "memory")
#define LDM4(r0, r1, r2, r3, a) asm volatile( \
    "ldmatrix.sync.aligned.m8n8.x4.shared.b16 {%0,%1,%2,%3}, [%4];" \
    : "=r"(r0), "=r"(r1), "=r"(r2), "=r"(r3) : "r"(a))

__device__ __forceinline__ uint32_t packh(float lo, float hi) {
    return (uint32_t)__half_as_ushort(__float2half_rn(lo)) |
           ((uint32_t)__half_as_ushort(__float2half_rn(hi)) << 16);
}
__device__ __forceinline__ void mma16816(float d[4], const uint4& a, uint32_t b0, uint32_t b1) {
    asm volatile("mma.sync.aligned.m16n8k16.row.col.f32.f16.f16.f32 "
                 "{%0,%1,%2,%3}, {%4,%5,%6,%7}, {%8,%9}, {%0,%1,%2,%3};\n"
                 : "+f"(d[0]), "+f"(d[1]), "+f"(d[2]), "+f"(d[3])
                 : "r"(a.x), "r"(a.y), "r"(a.z), "r"(a.w), "r"(b0), "r"(b1));
}

// ---------------- prep: fp16 A-fragments + wcg vectors ------------------------
// PERMUTED output rows: fragment row r = (lane>>2)+8*(j&1) carries orig channel
// strip*16 + 2*(lane>>2) + (j&1).
__global__ void prep_kernel(const float* __restrict__ phi1W1, const float* __restrict__ phi1W2,
                            const float* __restrict__ phiKW1, const float* __restrict__ phiKW2,
                            const float* __restrict__ g1W1,   const float* __restrict__ g1W2,
                            const float* __restrict__ gKW1,   const float* __restrict__ gKW2,
                            const float* __restrict__ g5W1) {
    const int id = blockIdx.x;
    if (id >= 18) {
        int w = id - 18, o = threadIdx.x;
        if (o < 64) {
            float v;
            if (w == 0) v = phi1W1[o * 2] + phi1W1[o * 2 + 1];
            else if (w <= 4) v = phiKW1[(w - 1) * 4160 + o * 65];
            else v = g1W1[o * 65];
            g_wcg[w * 64 + o] = v;
        }
        return;
    }
    const float* src; int off, KB, type;
    if (id == 0)       { src = phi1W2;              off = O_PHI1_W2;       KB = 4; type = 0; }
    else if (id < 5)   { int i = id - 1;  src = phiKW1 + i * 4160; off = O_PHIK_W1(i); KB = 4; type = 1; }
    else if (id < 9)   { int i = id - 5;  src = phiKW2 + i * 4096; off = O_PHIK_W2(i); KB = 4; type = 0; }
    else if (id == 9)  { src = g1W1;                off = O_G1_W1;         KB = 4; type = 4; }
    else if (id == 10) { src = g1W2;                off = O_G1_W2;         KB = 4; type = 0; }
    else if (id < 14)  { int i = id - 11; src = gKW1 + i * 8192;  off = O_GK_W1(i);  KB = 8; type = 5; }
    else if (id < 17)  { int i = id - 14; src = gKW2 + i * 4096;  off = O_GK_W2(i);  KB = 4; type = 0; }
    else               { src = g5W1;                off = O_G5_W1;         KB = 8; type = 5; }

    const float ninv = -1.0f / 63.0f;
    const int total = KB * 512;
    for (int e = threadIdx.x; e < total; e += blockDim.x) {
        int strip = e / (KB * 128);
        int rem   = e % (KB * 128);
        int kt = rem / 128;
        int r3 = rem & 127;
        int lane = r3 >> 2, j = r3 & 3;
        int o  = strip * 16 + 2 * (lane >> 2) + (j & 1);    // PERMUTED row map
        int k0 = kt * 16 + (lane & 3) * 2 + 8 * (j >> 1);
        float w0, w1;
        if (type == 0)      { w0 = src[o * 64 + k0];  w1 = src[o * 64 + k0 + 1]; }
        else if (type == 5) { w0 = src[o * 128 + k0]; w1 = src[o * 128 + k0 + 1];
                              if (k0 >= 64) { w0 *= ninv; w1 *= ninv; } }
        else if (type == 1) { w0 = src[o * 65 + 1 + k0]; w1 = src[o * 65 + 2 + k0]; }
        else                { w0 = src[o * 65 + 1 + k0] * ninv; w1 = src[o * 65 + 2 + k0] * ninv; }
        g_wfrag[off + e] = packh(w0, w1);
    }
}

__global__ void cgt_kernel(const float* __restrict__ cg) {
    const int b = blockIdx.x;
    for (int j = threadIdx.x; j < 4096; j += 256) {
        int a = j >> 6, u = j & 63;
        g_cgT[(b * 64 + a) * 64 + u] = cg[b * 4096 + u * 64 + a];
    }
}

// ---------------- sum over a of packed msgs ([u][c2] layout) ------------------
__global__ void asum_kernel() {
    const int b = blockIdx.x >> 3;
    const int e = (blockIdx.x & 7) * 256 + threadIdx.x;   // u*32 + c2
    const uint32_t* p0 = g_msgsP + (size_t)b * 131072 + e;
    float s0 = 0.f, s1 = 0.f;
#pragma unroll 8
    for (int a = 0; a < 64; ++a) {
        uint32_t h = p0[(size_t)a * 2048];
        __half2 hv = *reinterpret_cast<const __half2*>(&h);
        float2 f = __half22float2(hv);
        s0 += f.x; s1 += f.y;
    }
    int u = e >> 5, c2 = e & 31;
    g_sums[b * 4096 + (2 * c2) * 64 + u]     = s0;
    g_sums[b * 4096 + (2 * c2 + 1) * 64 + u] = s1;
}

// ---------------- per-b precompute: P = bias1 + (Wagg/63)*S -------------------
__global__ void pP_kernel(const float* __restrict__ Wsrc, const float* __restrict__ b1,
                          int CW, int cOff) {
    __shared__ float sWT[64 * 65];
    __shared__ float sS2[4096];
    const int b = blockIdx.x, t = threadIdx.x;
    for (int idx = t; idx < 4096; idx += 256) {
        int o = idx >> 6, c = idx & 63;
        sWT[c * 65 + o] = Wsrc[o * CW + cOff + c] * (1.0f / 63.0f);
        sS2[idx] = g_sums[b * 4096 + idx];
    }
    __syncthreads();
    const int o = t & 63, ublk = t >> 6;
    float acc[16];
    float bv = __ldg(b1 + o);
#pragma unroll
    for (int i = 0; i < 16; ++i) acc[i] = bv;
    const float4* S4 = (const float4*)sS2;
#pragma unroll 4
    for (int c = 0; c < 64; ++c) {
        float w = sWT[c * 65 + o];
#pragma unroll
        for (int i = 0; i < 4; ++i) {
            float4 s = S4[c * 16 + ublk * 4 + i];
            acc[i * 4 + 0] += w * s.x; acc[i * 4 + 1] += w * s.y;
            acc[i * 4 + 2] += w * s.z; acc[i * 4 + 3] += w * s.w;
        }
    }
    float4* P4 = (float4*)(g_P + b * 4096 + o * 64 + ublk * 16);
#pragma unroll
    for (int i = 0; i < 4; ++i)
        P4[i] = make_float4(acc[i * 4], acc[i * 4 + 1], acc[i * 4 + 2], acc[i * 4 + 3]);
}

// ---------------- cp.async prefetch ------------------------------------------
template<int MODE, int S1>
__device__ __forceinline__ void prefetch_slice(uint32_t dstB, int ba, int t2) {
    const uint32_t* rP = g_rP + (size_t)ba * 2048;
    const uint32_t* mP = g_msgsP + (size_t)ba * 2048;
    if (MODE == 3) {
        for (int cc = t2; cc < 64 * 16; cc += 128) {
            int row = cc >> 4, ch = cc & 15;
            const uint32_t* src = (ch < 8) ? (rP + row * 32 + ch * 4)
                                           : (mP + row * 32 + (ch - 8) * 4);
            CP_ASYNC16(dstB + (uint32_t)(row * S1 + ch * 4) * 4u, src);
        }
    } else {
        const uint32_t* base = (MODE == 1) ? rP : mP;
        for (int cc = t2; cc < 64 * 8; cc += 128) {
            int row = cc >> 3, ch = cc & 7;
            CP_ASYNC16(dstB + (uint32_t)(row * S1 + ch * 4) * 4u, base + row * 32 + ch * 4);
        }
    }
}

// ---------------- layer kernel -----------------------------------------------
// MODE: 0 phi1 (no conv1 mma), 1 phiK, 2 gamma1, 3 gammaK/gamma5
template<int KB1, int MODE, bool FINAL>
__global__ void __launch_bounds__(256, 2) layer_kernel(const float* __restrict__ b1v,
                                                       const float* __restrict__ b2v,
                                                       int w1off, int w2off, int wcgIdx,
                                                       const float* __restrict__ w2raw,
                                                       float* __restrict__ dout) {
    constexpr bool RELU2 = (MODE >= 2);
    constexpr int S1 = KB1 * 8 + 4;
    constexpr int BUFU = (KB1 > 0) ? 64 * S1 : 0;
    constexpr int W1U = (KB1 > 0) ? KB1 * 512 : 0;
    extern __shared__ uint32_t sm[];
    uint32_t* sW1f = sm;
    uint32_t* sX   = sW1f + W1U;
    uint32_t* sH   = sX + 4 * BUFU;
    float*    sRed = (float*)sH;

    const int t = threadIdx.x;
    const int warp = t >> 5, lane = t & 31, q = lane & 3, g = lane >> 2;
    const int half = warp >> 2, wl = warp & 3;
    const int t2 = t & 127;
    const int o2 = wl * 16 + 2 * g, o2p = o2 + 1;   // PERMUTED: lane owns channel pair
    const int c2i = wl * 8 + g;                     // channel-pair index
    const float inv = 1.0f / 63.0f;
    const int barid = 1 + half;
    const int row_lane = (lane & 7) + ((lane >> 4) << 3);
    const int kb_off = ((lane >> 3) & 1) * 4;

    uint32_t smbase;
    asm("{ .reg .u64 tmp; cvta.to.shared.u64 tmp, %1; cvt.u32.u64 %0, tmp; }"
        : "=r"(smbase) : "l"(sm));
    const uint32_t xbyte = smbase + (uint32_t)W1U * 4u;
    const uint32_t hbyte = smbase + (uint32_t)(W1U + 4 * BUFU + half * 2304) * 4u;
    uint32_t* sHh = sH + half * 2304;

    if (KB1 > 0) {
        const uint4* gw1 = (const uint4*)(g_wfrag + w1off);
        uint4* d1 = (uint4*)sW1f;
        for (int i = t; i < KB1 * 128; i += 256) d1[i] = gw1[i];
    }
    uint4 W2r[4];
    if (!FINAL) {
        const uint4* gw2 = (const uint4*)(g_wfrag + w2off);
#pragma unroll
        for (int kt = 0; kt < 4; ++kt) W2r[kt] = gw2[wl * 128 + kt * 32 + lane];
    }
    float bA1 = 0.f, bB1 = 0.f, bA2 = 0.f, bB2 = 0.f, w2a = 0.f, w2b = 0.f, bF = 0.f;
    float wA = 0.f, wB = 0.f;
    if (MODE < 2)  { bA1 = __ldg(b1v + o2); bB1 = __ldg(b1v + o2p); }
    if (MODE <= 2) { wA = g_wcg[wcgIdx * 64 + o2]; wB = g_wcg[wcgIdx * 64 + o2p]; }
    if (!FINAL)    { bA2 = __ldg(b2v + o2); bB2 = __ldg(b2v + o2p); }
    if (FINAL)     { w2a = __ldg(w2raw + o2); w2b = __ldg(w2raw + o2p); bF = __ldg(b2v); }

    {
        int tot = 4 * BUFU + (FINAL ? 512 : 2 * 2304);
        for (int i = t; i < tot; i += 256) sX[i] = 0;
    }
    __syncthreads();

    const int stride2 = gridDim.x * 2;
    const int stream = blockIdx.x * 2 + half;
    int o = 0;
    if (KB1 > 0) {
        if (stream < NBA)
            prefetch_slice<MODE, S1>(xbyte + (uint32_t)((half * 2) * BUFU) * 4u, stream, t2);
        CP_COMMIT();
    }

    uint32_t xadr0[4], hadr0[4];
#pragma unroll
    for (int ntp = 0; ntp < 4; ++ntp) {
        xadr0[ntp] = (uint32_t)(((ntp * 16 + row_lane) * S1 + kb_off) * 4);
        hadr0[ntp] = hbyte + (uint32_t)(((ntp * 16 + row_lane) * 36 + kb_off) * 4);
    }

    for (int ba = stream; ba < NBA; ba += stride2) {
        const int b = ba >> 6;
        if (KB1 > 0) {
            int nxt = ba + stride2;
            if (nxt < NBA)
                prefetch_slice<MODE, S1>(xbyte + (uint32_t)((half * 2 + (o ^ 1)) * BUFU) * 4u, nxt, t2);
            CP_COMMIT();
            CP_WAIT1();
            BARH(barid);
        }
        const uint32_t bufB = xbyte + (uint32_t)((half * 2 + o) * BUFU) * 4u;

        float2 cg2[8];
        if (MODE <= 2) {
            const float* cgp = g_cgT + ba * 64;
#pragma unroll
            for (int nt = 0; nt < 8; ++nt)
                cg2[nt] = __ldg((const float2*)(cgp + nt * 8 + q * 2));
        }

        // ---- conv1 ----
        float acc[8][4];
#pragma unroll
        for (int nt = 0; nt < 8; ++nt)
#pragma unroll
            for (int j = 0; j < 4; ++j) acc[nt][j] = 0.f;
        if (KB1 > 0) {
            const uint4* A1 = (const uint4*)sW1f + wl * (KB1 * 32);
#pragma unroll
            for (int kt = 0; kt < KB1; ++kt) {
                uint4 Ah = A1[kt * 32 + lane];
#pragma unroll
                for (int ntp = 0; ntp < 4; ++ntp) {
                    uint32_t b0a, b1a, b0b, b1b;
                    LDM4(b0a, b1a, b0b, b1b, bufB + xadr0[ntp] + kt * 32);
                    mma16816(acc[2 * ntp],     Ah, b0a, b1a);
                    mma16816(acc[2 * ntp + 1], Ah, b0b, b1b);
                }
            }
        }
        if (MODE >= 2) {
            const float* Pb = g_P + b * 4096;
#pragma unroll
            for (int nt = 0; nt < 8; ++nt) {
                int u0 = nt * 8 + q * 2;
                float2 pa = __ldg((const float2*)(Pb + o2 * 64 + u0));
                float2 pb = __ldg((const float2*)(Pb + o2p * 64 + u0));
                acc[nt][0] += pa.x; acc[nt][1] += pa.y;
                acc[nt][2] += pb.x; acc[nt][3] += pb.y;
            }
        } else {
#pragma unroll
            for (int nt = 0; nt < 8; ++nt) {
                acc[nt][0] += bA1; acc[nt][1] += bA1;
                acc[nt][2] += bB1; acc[nt][3] += bB1;
            }
        }
        if (MODE <= 2) {
#pragma unroll
            for (int nt = 0; nt < 8; ++nt) {
                acc[nt][0] += wA * cg2[nt].x; acc[nt][1] += wA * cg2[nt].y;
                acc[nt][2] += wB * cg2[nt].x; acc[nt][3] += wB * cg2[nt].y;
            }
        }
#pragma unroll
        for (int nt = 0; nt < 8; ++nt)
#pragma unroll
            for (int j = 0; j < 4; ++j) acc[nt][j] = fmaxf(acc[nt][j], 0.0f);
        float SA = 0.f, SB = 0.f;
#pragma unroll
        for (int nt = 0; nt < 8; ++nt) { SA += acc[nt][0] + acc[nt][1]; SB += acc[nt][2] + acc[nt][3]; }
        SA += __shfl_xor_sync(0xffffffffu, SA, 1); SA += __shfl_xor_sync(0xffffffffu, SA, 2);
        SB += __shfl_xor_sync(0xffffffffu, SB, 1); SB += __shfl_xor_sync(0xffffffffu, SB, 2);

        if (!FINAL) {
            // post + local pack (no shuffles): lane owns both channels of pair c2i
#pragma unroll
            for (int nt = 0; nt < 8; ++nt) {
                float t0, t1, t2v, t3;
                if (wl >= 2) {
                    t0 = (SA - acc[nt][0]) * inv; t1 = (SA - acc[nt][1]) * inv;
                    t2v = (SB - acc[nt][2]) * inv; t3 = (SB - acc[nt][3]) * inv;
                } else { t0 = acc[nt][0]; t1 = acc[nt][1]; t2v = acc[nt][2]; t3 = acc[nt][3]; }
                int u0 = nt * 8 + q * 2;
                sHh[u0 * 36 + c2i]       = packh(t0, t2v);
                sHh[(u0 + 1) * 36 + c2i] = packh(t1, t3);
            }
            BARH(barid);

            // ---- conv2 ----
            float a2[8][4];
#pragma unroll
            for (int nt = 0; nt < 8; ++nt)
#pragma unroll
                for (int j = 0; j < 4; ++j) a2[nt][j] = 0.f;
#pragma unroll
            for (int kt = 0; kt < 4; ++kt) {
#pragma unroll
                for (int ntp = 0; ntp < 4; ++ntp) {
                    uint32_t b0a, b1a, b0b, b1b;
                    LDM4(b0a, b1a, b0b, b1b, hadr0[ntp] + kt * 32);
                    mma16816(a2[2 * ntp],     W2r[kt], b0a, b1a);
                    mma16816(a2[2 * ntp + 1], W2r[kt], b0b, b1b);
                }
            }
#pragma unroll
            for (int nt = 0; nt < 8; ++nt) {
                a2[nt][0] += bA2; a2[nt][1] += bA2;
                a2[nt][2] += bB2; a2[nt][3] += bB2;
            }
            if (RELU2) {
#pragma unroll
                for (int nt = 0; nt < 8; ++nt)
#pragma unroll
                    for (int j = 0; j < 4; ++j) a2[nt][j] = fmaxf(a2[nt][j], 0.0f);
            }
            float S2A = 0.f, S2B = 0.f;
#pragma unroll
            for (int nt = 0; nt < 8; ++nt) { S2A += a2[nt][0] + a2[nt][1]; S2B += a2[nt][2] + a2[nt][3]; }
            S2A += __shfl_xor_sync(0xffffffffu, S2A, 1); S2A += __shfl_xor_sync(0xffffffffu, S2A, 2);
            S2B += __shfl_xor_sync(0xffffffffu, S2B, 1); S2B += __shfl_xor_sync(0xffffffffu, S2B, 2);

            uint32_t* gout = (RELU2 ? g_rP : g_msgsP) + (size_t)ba * 2048;
#pragma unroll
            for (int nt = 0; nt < 8; ++nt) {
                float t0, t1, t2v, t3;
                if (wl >= 2) {
                    t0 = (S2A - a2[nt][0]) * inv; t1 = (S2A - a2[nt][1]) * inv;
                    t2v = (S2B - a2[nt][2]) * inv; t3 = (S2B - a2[nt][3]) * inv;
                } else { t0 = a2[nt][0]; t1 = a2[nt][1]; t2v = a2[nt][2]; t3 = a2[nt][3]; }
                int u0 = nt * 8 + q * 2;
                gout[u0 * 32 + c2i]       = packh(t0, t2v);
                gout[(u0 + 1) * 32 + c2i] = packh(t1, t3);
            }
            if (KB1 == 0) BARH(barid);
        } else {
            // FINAL: GEMV partial + cross-warp reduce
#pragma unroll
            for (int nt = 0; nt < 8; ++nt) {
                float f0, f1, f2, f3;
                if (wl >= 2) {
                    f0 = (SA - acc[nt][0]) * inv; f1 = (SA - acc[nt][1]) * inv;
                    f2 = (SB - acc[nt][2]) * inv; f3 = (SB - acc[nt][3]) * inv;
                } else { f0 = acc[nt][0]; f1 = acc[nt][1]; f2 = acc[nt][2]; f3 = acc[nt][3]; }
                float p0 = w2a * f0 + w2b * f2;
                float p1 = w2a * f1 + w2b * f3;
                p0 += __shfl_xor_sync(0xffffffffu, p0, 4);
                p0 += __shfl_xor_sync(0xffffffffu, p0, 8);
                p0 += __shfl_xor_sync(0xffffffffu, p0, 16);
                p1 += __shfl_xor_sync(0xffffffffu, p1, 4);
                p1 += __shfl_xor_sync(0xffffffffu, p1, 8);
                p1 += __shfl_xor_sync(0xffffffffu, p1, 16);
                if (g == 0) {
                    int u0 = nt * 8 + q * 2;
                    sRed[half * 256 + wl * 64 + u0]     = p0;
                    sRed[half * 256 + wl * 64 + u0 + 1] = p1;
                }
            }
            BARH(barid);
            if (t2 < 64) {
                const float* R = sRed + half * 256;
                float sv = R[t2] + R[64 + t2] + R[128 + t2] + R[192 + t2];
                dout[b * 4096 + t2 * 64 + (ba & 63)] = sv + bF;
            }
            BARH(barid);
        }
        o ^= 1;
    }
}

// ---------------- launch -----------------------------------------------------
extern "C" void kernel_launch(void* const* d_in, const int* in_sizes, int n_in,
                              void* d_out, int out_size) {
    (void)in_sizes; (void)n_in; (void)out_size;
    const float* cg      = (const float*)d_in[0];
    const float* phi1_W1 = (const float*)d_in[1];
    const float* phi1_b1 = (const float*)d_in[2];
    const float* phi1_W2 = (const float*)d_in[3];
    const float* phi1_b2 = (const float*)d_in[4];
    const float* phiK_W1 = (const float*)d_in[5];
    const float* phiK_b1 = (const float*)d_in[6];
    const float* phiK_W2 = (const float*)d_in[7];
    const float* phiK_b2 = (const float*)d_in[8];
    const float* g1_W1   = (const float*)d_in[9];
    const float* g1_b1   = (const float*)d_in[10];
    const float* g1_W2   = (const float*)d_in[11];
    const float* g1_b2   = (const float*)d_in[12];
    const float* gK_W1   = (const float*)d_in[13];
    const float* gK_b1   = (const float*)d_in[14];
    const float* gK_W2   = (const float*)d_in[15];
    const float* gK_b2   = (const float*)d_in[16];
    const float* g5_W1   = (const float*)d_in[17];
    const float* g5_b1   = (const float*)d_in[18];
    const float* g5_W2   = (const float*)d_in[19];
    const float* g5_b2   = (const float*)d_in[20];
    float* out = (float*)d_out;

    auto smem_bytes = [](int KB1, bool fin) {
        int S1 = KB1 * 8 + 4;
        int BUFU = (KB1 > 0) ? 64 * S1 : 0;
        int W1U = (KB1 > 0) ? KB1 * 512 : 0;
        int u32s = W1U + 4 * BUFU + (fin ? 512 : 2 * 2304) + 16;
        return u32s * 4;
    };
    const int SM0 = smem_bytes(0, false);
    const int SM4 = smem_bytes(4, false);
    const int SM8 = smem_bytes(8, false);
    const int SMF = smem_bytes(8, true);

    cudaFuncSetAttribute(layer_kernel<0, 0, false>, cudaFuncAttributeMaxDynamicSharedMemorySize, SM0);
    cudaFuncSetAttribute(layer_kernel<4, 1, false>, cudaFuncAttributeMaxDynamicSharedMemorySize, SM4);
    cudaFuncSetAttribute(layer_kernel<4, 2, false>, cudaFuncAttributeMaxDynamicSharedMemorySize, SM4);
    cudaFuncSetAttribute(layer_kernel<8, 3, false>, cudaFuncAttributeMaxDynamicSharedMemorySize, SM8);
    cudaFuncSetAttribute(layer_kernel<8, 3, true>,  cudaFuncAttributeMaxDynamicSharedMemorySize, SMF);

    prep_kernel<<<24, 256>>>(phi1_W1, phi1_W2, phiK_W1, phiK_W2, g1_W1, g1_W2, gK_W1, gK_W2, g5_W1);
    cgt_kernel<<<128, 256>>>(cg);

    const int G = 296;

    layer_kernel<0, 0, false><<<G, 256, SM0>>>(phi1_b1, phi1_b2, 0, O_PHI1_W2, 0, nullptr, nullptr);
    asum_kernel<<<1024, 256>>>();
    pP_kernel<<<128, 256>>>(g1_W1, g1_b1, 65, 1);
    layer_kernel<4, 2, false><<<G, 256, SM4>>>(nullptr, g1_b2, O_G1_W1, O_G1_W2, 5, nullptr, nullptr);

    for (int i = 0; i < 4; ++i) {
        layer_kernel<4, 1, false><<<G, 256, SM4>>>(phiK_b1 + i * 64, phiK_b2 + i * 64,
                                                   O_PHIK_W1(i), O_PHIK_W2(i), 1 + i,
                                                   nullptr, nullptr);
        asum_kernel<<<1024, 256>>>();
        if (i < 3) {
            pP_kernel<<<128, 256>>>(gK_W1 + i * 8192, gK_b1 + i * 64, 128, 64);
            layer_kernel<8, 3, false><<<G, 256, SM8>>>(nullptr, gK_b2 + i * 64,
                                                       O_GK_W1(i), O_GK_W2(i), 0,
                                                       nullptr, nullptr);
        } else {
            pP_kernel<<<128, 256>>>(g5_W1, g5_b1, 128, 64);
            layer_kernel<8, 3, true><<<G, 256, SMF>>>(nullptr, g5_b2,
                                                      O_G5_W1, 0, 0, g5_W2, out);
        }
    }
}